// round 6
// baseline (speedup 1.0000x reference)
#include <cuda_runtime.h>

__device__ double g_loss;
__device__ double g_denom;

__global__ void zero_accum_kernel() {
    g_loss = 0.0;
    g_denom = 0.0;
}

// Tile: 128 px wide x 8 rows. Block: (32, 8) = 256 threads, 4 px per thread.
// Requires W % 128 == 0 and H % 8 == 0 (1280, 384 -> exact).
#define TILE_W 128
#define TILE_H 8
#define HROWS  (TILE_H + 2)     // 10
#define ROWPAD 132              // 130 used cols (x0-1 .. x0+128), padded
#define NTHREADS 256

__global__ __launch_bounds__(NTHREADS) void normal_loss_kernel(
    const float* __restrict__ pred,
    const float* __restrict__ gt,
    const float* __restrict__ mask,
    int H, int W)
{
    __shared__ float s[2][3][HROWS][ROWPAD];
    __shared__ float red_l[NTHREADS / 32];
    __shared__ float red_m[NTHREADS / 32];

    const int b  = blockIdx.z;
    const int x0 = blockIdx.x * TILE_W;
    const int y0 = blockIdx.y * TILE_H;
    const int tx = threadIdx.x;           // 0..31
    const int ty = threadIdx.y;           // 0..7
    const int tid = ty * 32 + tx;
    const int warp = tid >> 5;            // == ty
    const int lane = tid & 31;            // == tx

    const int plane = H * W;              // fits in int (384*1280)
    const float* pb = pred + (size_t)b * 3 * plane;
    const float* gb = gt   + (size_t)b * 3 * plane;
    const float* mb = mask + (size_t)b * plane;

    // ---- Halo load: 60 warp-tasks = 2 tensors x 3 ch x 10 rows ----
    // Each task: one warp loads 128 floats as float4 + 2 scalar halo cols.
    for (int t = warp; t < 60; t += 8) {
        const int tens = t / 30;
        const int rem  = t - tens * 30;
        const int ch   = rem / 10;
        const int r    = rem - ch * 10;
        const int gy   = y0 + r - 1;
        const bool inrow = (gy >= 0) && (gy < H);

        const float* src = (tens == 0 ? pb : gb) + ch * plane;
        float* __restrict__ srow = &s[tens][ch][r][0];

        float4 v = make_float4(0.f, 0.f, 0.f, 0.f);
        if (inrow) {
            v = *(const float4*)(src + gy * W + x0 + 4 * lane);
        }
        srow[1 + 4 * lane + 0] = v.x;
        srow[1 + 4 * lane + 1] = v.y;
        srow[1 + 4 * lane + 2] = v.z;
        srow[1 + 4 * lane + 3] = v.w;
        if (lane == 0)
            srow[0]   = (inrow && x0 > 0)            ? src[gy * W + x0 - 1]   : 0.f;
        if (lane == 1)
            srow[129] = (inrow && x0 + TILE_W < W)   ? src[gy * W + x0 + 128] : 0.f;
    }
    __syncthreads();

    // ---- Compute: thread handles 4 px at local x = 4*tx .. 4*tx+3, row ty ----
    const int r  = ty + 1;
    const int c0 = 4 * tx;          // smem col of (px0 - 1); 16B aligned

    float pnx[4], pny[4], pnz[4];
    float lsum = 0.f, msum = 0.f;

    #pragma unroll
    for (int tens = 0; tens < 2; tens++) {
        float GX[3][4], GY[3][4];
        #pragma unroll
        for (int ch = 0; ch < 3; ch++) {
            const float* rm = &s[tens][ch][r - 1][c0];
            const float* rc = &s[tens][ch][r    ][c0];
            const float* rp = &s[tens][ch][r + 1][c0];
            float cs[6], rd[6];
            #pragma unroll
            for (int j = 0; j < 6; j++) {
                float a = rm[j], m = rc[j], p = rp[j];
                cs[j] = a + m + p;    // column sum
                rd[j] = p - a;        // row diff
            }
            #pragma unroll
            for (int i = 0; i < 4; i++) {
                GX[ch][i] = 3.f * (cs[i + 2] - cs[i]);
                GY[ch][i] = 3.f * (rd[i] + rd[i + 1] + rd[i + 2]);
            }
        }
        if (tens == 0) {
            #pragma unroll
            for (int i = 0; i < 4; i++) {
                float nx = GX[1][i] * GY[2][i] - GX[2][i] * GY[1][i];
                float ny = GX[2][i] * GY[0][i] - GX[0][i] * GY[2][i];
                float nz = GX[0][i] * GY[1][i] - GX[1][i] * GY[0][i];
                float inv = 1.f / (sqrtf(nx * nx + ny * ny + nz * nz) + 1e-10f);
                pnx[i] = nx * inv; pny[i] = ny * inv; pnz[i] = nz * inv;
            }
        } else {
            const int py = y0 + ty;
            float4 mv = *(const float4*)(mb + py * W + x0 + c0);
            float mm[4] = {mv.x, mv.y, mv.z, mv.w};
            #pragma unroll
            for (int i = 0; i < 4; i++) {
                float nx = GX[1][i] * GY[2][i] - GX[2][i] * GY[1][i];
                float ny = GX[2][i] * GY[0][i] - GX[0][i] * GY[2][i];
                float nz = GX[0][i] * GY[1][i] - GX[1][i] * GY[0][i];
                float inv = 1.f / (sqrtf(nx * nx + ny * ny + nz * nz) + 1e-10f);
                nx *= inv; ny *= inv; nz *= inv;
                lsum += mm[i] * (fabsf(pnx[i] - nx) + fabsf(pny[i] - ny) + fabsf(pnz[i] - nz));
                msum += mm[i];
            }
        }
    }

    // ---- Block reduction ----
    #pragma unroll
    for (int o = 16; o > 0; o >>= 1) {
        lsum += __shfl_down_sync(0xFFFFFFFFu, lsum, o);
        msum += __shfl_down_sync(0xFFFFFFFFu, msum, o);
    }
    if (lane == 0) {
        red_l[warp] = lsum;
        red_m[warp] = msum;
    }
    __syncthreads();
    if (tid == 0) {
        float tl = 0.f, tm = 0.f;
        #pragma unroll
        for (int w = 0; w < NTHREADS / 32; w++) {
            tl += red_l[w];
            tm += red_m[w];
        }
        atomicAdd(&g_loss, (double)tl);
        atomicAdd(&g_denom, (double)tm);
    }
}

__global__ void finalize_kernel(float* __restrict__ out) {
    out[0] = (float)(g_loss / g_denom);
}

extern "C" void kernel_launch(void* const* d_in, const int* in_sizes, int n_in,
                              void* d_out, int out_size)
{
    const float* pred = (const float*)d_in[0];
    const float* gt   = (const float*)d_in[1];
    const float* mask = (const float*)d_in[2];
    float* out = (float*)d_out;

    const int H = 384;
    const int W = 1280;
    const int B = in_sizes[2] / (H * W);

    zero_accum_kernel<<<1, 1>>>();

    dim3 block(32, TILE_H);
    dim3 grid(W / TILE_W, H / TILE_H, B);
    normal_loss_kernel<<<grid, block>>>(pred, gt, mask, H, W);

    finalize_kernel<<<1, 1>>>(out);
}

// round 7
// speedup vs baseline: 1.4683x; 1.4683x over previous
#include <cuda_runtime.h>

__device__ double g_loss;
__device__ double g_denom;

__global__ void zero_accum_kernel() {
    g_loss = 0.0;
    g_denom = 0.0;
}

// Tile: 128 px wide x 8 rows. Block: (32, 8) = 256 threads, 4 px per thread.
// Requires W % 128 == 0 and H % 8 == 0 (1280, 384 -> exact).
#define TILE_W 128
#define TILE_H 8
#define HROWS  (TILE_H + 2)     // 10
#define ROWPAD 132              // 130 used cols (x0-1 .. x0+128); 132*4B row = 16B aligned
#define NTHREADS 256

__global__ __launch_bounds__(NTHREADS) void normal_loss_kernel(
    const float* __restrict__ pred,
    const float* __restrict__ gt,
    const float* __restrict__ mask,
    int H, int W)
{
    __shared__ float s[2][3][HROWS][ROWPAD];
    __shared__ float red_l[NTHREADS / 32];
    __shared__ float red_m[NTHREADS / 32];

    const int b  = blockIdx.z;
    const int x0 = blockIdx.x * TILE_W;
    const int y0 = blockIdx.y * TILE_H;
    const int tx = threadIdx.x;           // 0..31
    const int ty = threadIdx.y;           // 0..7
    const int tid = ty * 32 + tx;
    const int warp = tid >> 5;            // == ty
    const int lane = tid & 31;            // == tx

    const int plane = H * W;
    const float* pb = pred + (size_t)b * 3 * plane;
    const float* gb = gt   + (size_t)b * 3 * plane;
    const float* mb = mask + (size_t)b * plane;

    // ---- Halo load: 60 warp-tasks = 2 tensors x 3 ch x 10 rows ----
    for (int t = warp; t < 60; t += 8) {
        const int tens = t / 30;
        const int rem  = t - tens * 30;
        const int ch   = rem / 10;
        const int r    = rem - ch * 10;
        const int gy   = y0 + r - 1;
        const bool inrow = (gy >= 0) && (gy < H);

        const float* src = (tens == 0 ? pb : gb) + ch * plane;
        float* __restrict__ srow = &s[tens][ch][r][0];

        float4 v = make_float4(0.f, 0.f, 0.f, 0.f);
        if (inrow) {
            v = *(const float4*)(src + gy * W + x0 + 4 * lane);
        }
        srow[1 + 4 * lane + 0] = v.x;
        srow[1 + 4 * lane + 1] = v.y;
        srow[1 + 4 * lane + 2] = v.z;
        srow[1 + 4 * lane + 3] = v.w;
        if (lane == 0)
            srow[0]   = (inrow && x0 > 0)            ? src[gy * W + x0 - 1]   : 0.f;
        if (lane == 1)
            srow[129] = (inrow && x0 + TILE_W < W)   ? src[gy * W + x0 + 128] : 0.f;
    }
    __syncthreads();

    // ---- Compute: thread handles 4 px at local x = 4*tx .. 4*tx+3, row ty ----
    const int r  = ty + 1;
    const int c0 = 4 * tx;          // smem col of (px0 - 1); 16B aligned

    float pnx[4], pny[4], pnz[4];
    float lsum = 0.f, msum = 0.f;

    #pragma unroll
    for (int tens = 0; tens < 2; tens++) {
        float GX[3][4], GY[3][4];
        #pragma unroll
        for (int ch = 0; ch < 3; ch++) {
            // Explicit vector LDS.128: conflict-free (16B stride across lanes).
            const float4* rm4 = (const float4*)&s[tens][ch][r - 1][c0];
            const float4* rc4 = (const float4*)&s[tens][ch][r    ][c0];
            const float4* rp4 = (const float4*)&s[tens][ch][r + 1][c0];
            float am[8], ac[8], ap[8];
            *(float4*)&am[0] = rm4[0]; *(float4*)&am[4] = rm4[1];
            *(float4*)&ac[0] = rc4[0]; *(float4*)&ac[4] = rc4[1];
            *(float4*)&ap[0] = rp4[0]; *(float4*)&ap[4] = rp4[1];

            float cs[6], rd[6];
            #pragma unroll
            for (int j = 0; j < 6; j++) {
                cs[j] = am[j] + ac[j] + ap[j];   // column sum
                rd[j] = ap[j] - am[j];           // row diff
            }
            #pragma unroll
            for (int i = 0; i < 4; i++) {
                GX[ch][i] = 3.f * (cs[i + 2] - cs[i]);
                GY[ch][i] = 3.f * (rd[i] + rd[i + 1] + rd[i + 2]);
            }
        }
        if (tens == 0) {
            #pragma unroll
            for (int i = 0; i < 4; i++) {
                float nx = GX[1][i] * GY[2][i] - GX[2][i] * GY[1][i];
                float ny = GX[2][i] * GY[0][i] - GX[0][i] * GY[2][i];
                float nz = GX[0][i] * GY[1][i] - GX[1][i] * GY[0][i];
                float inv = rsqrtf(nx * nx + ny * ny + nz * nz + 1e-20f);
                pnx[i] = nx * inv; pny[i] = ny * inv; pnz[i] = nz * inv;
            }
        } else {
            const int py = y0 + ty;
            float4 mv = *(const float4*)(mb + py * W + x0 + c0);
            float mm[4] = {mv.x, mv.y, mv.z, mv.w};
            #pragma unroll
            for (int i = 0; i < 4; i++) {
                float nx = GX[1][i] * GY[2][i] - GX[2][i] * GY[1][i];
                float ny = GX[2][i] * GY[0][i] - GX[0][i] * GY[2][i];
                float nz = GX[0][i] * GY[1][i] - GX[1][i] * GY[0][i];
                float inv = rsqrtf(nx * nx + ny * ny + nz * nz + 1e-20f);
                nx *= inv; ny *= inv; nz *= inv;
                lsum += mm[i] * (fabsf(pnx[i] - nx) + fabsf(pny[i] - ny) + fabsf(pnz[i] - nz));
                msum += mm[i];
            }
        }
    }

    // ---- Block reduction ----
    #pragma unroll
    for (int o = 16; o > 0; o >>= 1) {
        lsum += __shfl_down_sync(0xFFFFFFFFu, lsum, o);
        msum += __shfl_down_sync(0xFFFFFFFFu, msum, o);
    }
    if (lane == 0) {
        red_l[warp] = lsum;
        red_m[warp] = msum;
    }
    __syncthreads();
    if (tid == 0) {
        float tl = 0.f, tm = 0.f;
        #pragma unroll
        for (int w = 0; w < NTHREADS / 32; w++) {
            tl += red_l[w];
            tm += red_m[w];
        }
        atomicAdd(&g_loss, (double)tl);
        atomicAdd(&g_denom, (double)tm);
    }
}

__global__ void finalize_kernel(float* __restrict__ out) {
    out[0] = (float)(g_loss / g_denom);
}

extern "C" void kernel_launch(void* const* d_in, const int* in_sizes, int n_in,
                              void* d_out, int out_size)
{
    const float* pred = (const float*)d_in[0];
    const float* gt   = (const float*)d_in[1];
    const float* mask = (const float*)d_in[2];
    float* out = (float*)d_out;

    const int H = 384;
    const int W = 1280;
    const int B = in_sizes[2] / (H * W);

    zero_accum_kernel<<<1, 1>>>();

    dim3 block(32, TILE_H);
    dim3 grid(W / TILE_W, H / TILE_H, B);
    normal_loss_kernel<<<grid, block>>>(pred, gt, mask, H, W);

    finalize_kernel<<<1, 1>>>(out);
}

// round 10
// speedup vs baseline: 2.3020x; 1.5678x over previous
#include <cuda_runtime.h>

#define TILE_W 128
#define TILE_H 8
#define HROWS  (TILE_H + 2)      // 10
#define ROWPAD 132               // 130 used cols; row base 16B aligned
#define NTHREADS 256
#define MAXB 8192

__device__ float2 g_part[MAXB];
__device__ unsigned int g_done = 0;   // self-resetting -> graph-replay safe

__global__ __launch_bounds__(NTHREADS) void normal_loss_kernel(
    const float* __restrict__ pred,
    const float* __restrict__ gt,
    const float* __restrict__ mask,
    float* __restrict__ out,
    int H, int W, int nblocks)
{
    __shared__ float s[2][3][HROWS][ROWPAD];
    __shared__ float red_l[NTHREADS / 32];
    __shared__ float red_m[NTHREADS / 32];
    __shared__ double dred_l[NTHREADS / 32];
    __shared__ double dred_m[NTHREADS / 32];
    __shared__ int s_last;

    const int b  = blockIdx.z;
    const int x0 = blockIdx.x * TILE_W;
    const int y0 = blockIdx.y * TILE_H;
    const int tx = threadIdx.x;           // 0..31
    const int ty = threadIdx.y;           // 0..7
    const int tid = ty * 32 + tx;
    const int warp = tid >> 5;
    const int lane = tid & 31;

    const int plane = H * W;
    const float* pb = pred + (size_t)b * 3 * plane;
    const float* gb = gt   + (size_t)b * 3 * plane;
    const float* mb = mask + (size_t)b * plane;

    // ---- Halo load: 60 rows x 128 floats = 1920 float4 tasks, flattened.
    // 8 independent LDG.128 per thread, all issued before any STS (high MLP).
    // Interior SMEM cols are 1..128 (left halo at col 0), so interior stores
    // are 4x STS.32 (byte offset 4+16*l5 is NOT 16B-aligned; STS.128 traps).
    float4 v[8];
    float* sp4[8];
    #pragma unroll
    for (int k = 0; k < 8; k++) {
        const int idx = tid + k * NTHREADS;        // < 2048; active if < 1920
        const bool act = (k < 7) || (tid < 128);
        const int t   = idx >> 5;                  // row-task 0..59
        const int l5  = idx & 31;
        const int tens = (t >= 30) ? 1 : 0;
        const int rem  = t - tens * 30;
        const int ch   = rem / 10;
        const int r    = rem - ch * 10;
        const int gy   = y0 + r - 1;
        const bool inrow = act && (gy >= 0) && (gy < H);
        const float* src = (tens ? gb : pb) + ch * plane;
        v[k] = make_float4(0.f, 0.f, 0.f, 0.f);
        if (inrow) v[k] = *(const float4*)(src + gy * W + x0 + 4 * l5);
        sp4[k] = &s[tens][ch][r][1 + 4 * l5];
    }
    // Edge columns: 60 rows x 2 cols = 120 scalar tasks on first 120 threads.
    float ev = 0.f;
    float* ep = nullptr;
    if (tid < 120) {
        const int t    = tid >> 1;
        const int side = tid & 1;
        const int tens = (t >= 30) ? 1 : 0;
        const int rem  = t - tens * 30;
        const int ch   = rem / 10;
        const int r    = rem - ch * 10;
        const int gy   = y0 + r - 1;
        const int gx   = side ? (x0 + TILE_W) : (x0 - 1);
        const float* src = (tens ? gb : pb) + ch * plane;
        if (gy >= 0 && gy < H && gx >= 0 && gx < W) ev = src[gy * W + gx];
        ep = &s[tens][ch][r][side ? (TILE_W + 1) : 0];
    }
    #pragma unroll
    for (int k = 0; k < 8; k++) {
        if (k == 7 && tid >= 128) break;
        sp4[k][0] = v[k].x;
        sp4[k][1] = v[k].y;
        sp4[k][2] = v[k].z;
        sp4[k][3] = v[k].w;
    }
    if (ep) *ep = ev;
    __syncthreads();

    // ---- Compute: thread handles 4 px at local x = 4*tx .. 4*tx+3, row ty ----
    const int r  = ty + 1;
    const int c0 = 4 * tx;          // 16B-aligned smem col of (px0 - 1)

    float pnx[4], pny[4], pnz[4];
    float lsum = 0.f, msum = 0.f;

    #pragma unroll
    for (int tens = 0; tens < 2; tens++) {
        float GX[3][4], GY[3][4];
        #pragma unroll
        for (int ch = 0; ch < 3; ch++) {
            const float4* rm4 = (const float4*)&s[tens][ch][r - 1][c0];
            const float4* rc4 = (const float4*)&s[tens][ch][r    ][c0];
            const float4* rp4 = (const float4*)&s[tens][ch][r + 1][c0];
            float am[8], ac[8], ap[8];
            *(float4*)&am[0] = rm4[0]; *(float4*)&am[4] = rm4[1];
            *(float4*)&ac[0] = rc4[0]; *(float4*)&ac[4] = rc4[1];
            *(float4*)&ap[0] = rp4[0]; *(float4*)&ap[4] = rp4[1];

            float cs[6], rd[6];
            #pragma unroll
            for (int j = 0; j < 6; j++) {
                cs[j] = am[j] + ac[j] + ap[j];
                rd[j] = ap[j] - am[j];
            }
            #pragma unroll
            for (int i = 0; i < 4; i++) {
                GX[ch][i] = cs[i + 2] - cs[i];                 // uniform 3x scale cancels
                GY[ch][i] = rd[i] + rd[i + 1] + rd[i + 2];
            }
        }
        if (tens == 0) {
            #pragma unroll
            for (int i = 0; i < 4; i++) {
                float nx = GX[1][i] * GY[2][i] - GX[2][i] * GY[1][i];
                float ny = GX[2][i] * GY[0][i] - GX[0][i] * GY[2][i];
                float nz = GX[0][i] * GY[1][i] - GX[1][i] * GY[0][i];
                float inv = rsqrtf(nx * nx + ny * ny + nz * nz + 1e-20f);
                pnx[i] = nx * inv; pny[i] = ny * inv; pnz[i] = nz * inv;
            }
        } else {
            const int py = y0 + ty;
            float4 mv = *(const float4*)(mb + py * W + x0 + c0);
            float mm[4] = {mv.x, mv.y, mv.z, mv.w};
            #pragma unroll
            for (int i = 0; i < 4; i++) {
                float nx = GX[1][i] * GY[2][i] - GX[2][i] * GY[1][i];
                float ny = GX[2][i] * GY[0][i] - GX[0][i] * GY[2][i];
                float nz = GX[0][i] * GY[1][i] - GX[1][i] * GY[0][i];
                float inv = rsqrtf(nx * nx + ny * ny + nz * nz + 1e-20f);
                nx *= inv; ny *= inv; nz *= inv;
                lsum += mm[i] * (fabsf(pnx[i] - nx) + fabsf(pny[i] - ny) + fabsf(pnz[i] - nz));
                msum += mm[i];
            }
        }
    }

    // ---- Block reduction -> per-block partial ----
    #pragma unroll
    for (int o = 16; o > 0; o >>= 1) {
        lsum += __shfl_down_sync(0xFFFFFFFFu, lsum, o);
        msum += __shfl_down_sync(0xFFFFFFFFu, msum, o);
    }
    if (lane == 0) { red_l[warp] = lsum; red_m[warp] = msum; }
    __syncthreads();

    const int bid = (blockIdx.z * gridDim.y + blockIdx.y) * gridDim.x + blockIdx.x;
    if (tid == 0) {
        float tl = 0.f, tm = 0.f;
        #pragma unroll
        for (int w = 0; w < NTHREADS / 32; w++) { tl += red_l[w]; tm += red_m[w]; }
        g_part[bid] = make_float2(tl, tm);
        __threadfence();
        unsigned int old = atomicAdd(&g_done, 1u);
        s_last = (old == (unsigned)(nblocks - 1)) ? 1 : 0;
    }
    __syncthreads();

    // ---- Last block: final reduction + output + counter reset ----
    if (s_last) {
        double dl = 0.0, dm = 0.0;
        for (int i = tid; i < nblocks; i += NTHREADS) {
            float2 p = __ldcg(&g_part[i]);
            dl += (double)p.x; dm += (double)p.y;
        }
        #pragma unroll
        for (int o = 16; o > 0; o >>= 1) {
            dl += __shfl_down_sync(0xFFFFFFFFu, dl, o);
            dm += __shfl_down_sync(0xFFFFFFFFu, dm, o);
        }
        if (lane == 0) { dred_l[warp] = dl; dred_m[warp] = dm; }
        __syncthreads();
        if (tid == 0) {
            double tl = 0.0, tm = 0.0;
            #pragma unroll
            for (int w = 0; w < NTHREADS / 32; w++) { tl += dred_l[w]; tm += dred_m[w]; }
            out[0] = (float)(tl / tm);
            g_done = 0;   // restore for next graph replay
        }
    }
}

extern "C" void kernel_launch(void* const* d_in, const int* in_sizes, int n_in,
                              void* d_out, int out_size)
{
    const float* pred = (const float*)d_in[0];
    const float* gt   = (const float*)d_in[1];
    const float* mask = (const float*)d_in[2];
    float* out = (float*)d_out;

    const int H = 384;
    const int W = 1280;
    const int B = in_sizes[2] / (H * W);

    dim3 block(32, TILE_H);
    dim3 grid(W / TILE_W, H / TILE_H, B);
    const int nblocks = grid.x * grid.y * grid.z;

    normal_loss_kernel<<<grid, block>>>(pred, gt, mask, out, H, W, nblocks);
}

// round 13
// speedup vs baseline: 2.8213x; 1.2256x over previous
#include <cuda_runtime.h>

#define TILE_W 128
#define TILE_H 16
#define HROWS  (TILE_H + 2)      // 18
#define ROWPAD 132               // cols: 0=left halo, 1..128 interior, 129 right halo
#define NTHREADS 256
#define MAXB 8192

__device__ float2 g_part[MAXB];
__device__ unsigned int g_done = 0;   // self-resetting -> graph-replay safe

// Load one tensor's 3 channels x 18 halo rows into s[3][HROWS][ROWPAD].
// 54 row-tasks x 32 lanes = 1728 float4 tasks; 7 batched independent LDG.128
// per thread (high MLP), scalar STS (interior col 1 start is not 16B aligned).
__device__ __forceinline__ void load_tile(
    float (*s)[HROWS][ROWPAD],
    const float* __restrict__ src0, int plane,
    int x0, int y0, int H, int W, int tid)
{
    float4 v[7];
    int   tt[7], rr[7], ll[7];
    #pragma unroll
    for (int k = 0; k < 7; k++) {
        int idx = tid + k * NTHREADS;            // < 1792; active if < 1728
        const bool act = (k < 6) || (tid < 192);
        int t  = idx >> 5; if (t > 53) t = 53;
        const int l5 = idx & 31;
        const int ch = t / 18;
        const int r  = t - ch * 18;
        const int gy = y0 + r - 1;
        const bool inrow = act && (gy >= 0) && (gy < H);
        v[k] = make_float4(0.f, 0.f, 0.f, 0.f);
        if (inrow) v[k] = *(const float4*)(src0 + ch * plane + gy * W + x0 + 4 * l5);
        tt[k] = ch; rr[k] = r; ll[k] = l5;
    }
    // Edge columns: 54 rows x 2 sides = 108 scalar tasks.
    float ev = 0.f;
    int ech = 0, er = 0, ecol = 0;
    bool has_e = (tid < 108);
    if (has_e) {
        const int t    = tid >> 1;
        const int side = tid & 1;
        ech = t / 18;
        er  = t - ech * 18;
        const int gy = y0 + er - 1;
        const int gx = side ? (x0 + TILE_W) : (x0 - 1);
        if (gy >= 0 && gy < H && gx >= 0 && gx < W)
            ev = src0[ech * plane + gy * W + gx];
        ecol = side ? (TILE_W + 1) : 0;
    }
    #pragma unroll
    for (int k = 0; k < 7; k++) {
        if (k == 6 && tid >= 192) break;
        float* p = &s[tt[k]][rr[k]][1 + 4 * ll[k]];
        p[0] = v[k].x; p[1] = v[k].y; p[2] = v[k].z; p[3] = v[k].w;
    }
    if (has_e) s[ech][er][ecol] = ev;
}

// Compute GX/GY for both output rows (r0, r0+1) of all 3 channels.
__device__ __forceinline__ void grads_2rows(
    const float (*s)[HROWS][ROWPAD], int r0, int c0,
    float GX0[3][4], float GY0[3][4], float GX1[3][4], float GY1[3][4])
{
    #pragma unroll
    for (int ch = 0; ch < 3; ch++) {
        float A[8], B[8], C[8], D[8];
        const float4* a4 = (const float4*)&s[ch][r0 - 1][c0];
        const float4* b4 = (const float4*)&s[ch][r0    ][c0];
        const float4* c4 = (const float4*)&s[ch][r0 + 1][c0];
        const float4* d4 = (const float4*)&s[ch][r0 + 2][c0];
        *(float4*)&A[0] = a4[0]; *(float4*)&A[4] = a4[1];
        *(float4*)&B[0] = b4[0]; *(float4*)&B[4] = b4[1];
        *(float4*)&C[0] = c4[0]; *(float4*)&C[4] = c4[1];
        *(float4*)&D[0] = d4[0]; *(float4*)&D[4] = d4[1];

        float cs0[6], rd0[6], cs1[6], rd1[6];
        #pragma unroll
        for (int j = 0; j < 6; j++) {
            const float bc = B[j] + C[j];
            cs0[j] = A[j] + bc;        // rows r0-1..r0+1
            rd0[j] = C[j] - A[j];
            cs1[j] = bc + D[j];        // rows r0..r0+2
            rd1[j] = D[j] - B[j];
        }
        #pragma unroll
        for (int i = 0; i < 4; i++) {
            GX0[ch][i] = cs0[i + 2] - cs0[i];
            GY0[ch][i] = rd0[i] + rd0[i + 1] + rd0[i + 2];
            GX1[ch][i] = cs1[i + 2] - cs1[i];
            GY1[ch][i] = rd1[i] + rd1[i + 1] + rd1[i + 2];
        }
    }
}

__device__ __forceinline__ void cross_norm(
    const float GX[3][4], const float GY[3][4],
    float* nxo, float* nyo, float* nzo)
{
    #pragma unroll
    for (int i = 0; i < 4; i++) {
        float nx = GX[1][i] * GY[2][i] - GX[2][i] * GY[1][i];
        float ny = GX[2][i] * GY[0][i] - GX[0][i] * GY[2][i];
        float nz = GX[0][i] * GY[1][i] - GX[1][i] * GY[0][i];
        float inv = rsqrtf(nx * nx + ny * ny + nz * nz + 1e-20f);
        nxo[i] = nx * inv; nyo[i] = ny * inv; nzo[i] = nz * inv;
    }
}

__global__ __launch_bounds__(NTHREADS, 3) void normal_loss_kernel(
    const float* __restrict__ pred,
    const float* __restrict__ gt,
    const float* __restrict__ mask,
    float* __restrict__ out,
    int H, int W, int nblocks)
{
    __shared__ float s[3][HROWS][ROWPAD];        // 28.5 KB, reused for both tensors
    __shared__ float red_l[NTHREADS / 32];
    __shared__ float red_m[NTHREADS / 32];
    __shared__ double dred_l[NTHREADS / 32];
    __shared__ double dred_m[NTHREADS / 32];
    __shared__ int s_last;

    const int b  = blockIdx.z;
    const int x0 = blockIdx.x * TILE_W;
    const int y0 = blockIdx.y * TILE_H;
    const int tx = threadIdx.x;           // 0..31
    const int ty = threadIdx.y;           // 0..7
    const int tid = ty * 32 + tx;
    const int warp = tid >> 5;
    const int lane = tid & 31;

    const int plane = H * W;
    const float* pb = pred + (size_t)b * 3 * plane;
    const float* gb = gt   + (size_t)b * 3 * plane;
    const float* mb = mask + (size_t)b * plane;

    const int r0 = 2 * ty + 1;            // smem row of first output row
    const int c0 = 4 * tx;                // 16B-aligned

    // ---- Phase P: pred ----
    load_tile(s, pb, plane, x0, y0, H, W, tid);
    __syncthreads();

    float pnx[8], pny[8], pnz[8];
    {
        float GX0[3][4], GY0[3][4], GX1[3][4], GY1[3][4];
        grads_2rows(s, r0, c0, GX0, GY0, GX1, GY1);
        cross_norm(GX0, GY0, &pnx[0], &pny[0], &pnz[0]);
        cross_norm(GX1, GY1, &pnx[4], &pny[4], &pnz[4]);
    }
    __syncthreads();

    // ---- Phase G: gt (reuse smem) ----
    load_tile(s, gb, plane, x0, y0, H, W, tid);
    __syncthreads();

    float lsum = 0.f, msum = 0.f;
    {
        float GX0[3][4], GY0[3][4], GX1[3][4], GY1[3][4];
        grads_2rows(s, r0, c0, GX0, GY0, GX1, GY1);
        float gnx[8], gny[8], gnz[8];
        cross_norm(GX0, GY0, &gnx[0], &gny[0], &gnz[0]);
        cross_norm(GX1, GY1, &gnx[4], &gny[4], &gnz[4]);

        const int py = y0 + 2 * ty;
        float4 m0 = *(const float4*)(mb + py * W + x0 + c0);
        float4 m1 = *(const float4*)(mb + (py + 1) * W + x0 + c0);
        float mm[8] = {m0.x, m0.y, m0.z, m0.w, m1.x, m1.y, m1.z, m1.w};
        #pragma unroll
        for (int i = 0; i < 8; i++) {
            lsum += mm[i] * (fabsf(pnx[i] - gnx[i]) + fabsf(pny[i] - gny[i])
                           + fabsf(pnz[i] - gnz[i]));
            msum += mm[i];
        }
    }

    // ---- Block reduction -> per-block partial ----
    #pragma unroll
    for (int o = 16; o > 0; o >>= 1) {
        lsum += __shfl_down_sync(0xFFFFFFFFu, lsum, o);
        msum += __shfl_down_sync(0xFFFFFFFFu, msum, o);
    }
    if (lane == 0) { red_l[warp] = lsum; red_m[warp] = msum; }
    __syncthreads();

    const int bid = (blockIdx.z * gridDim.y + blockIdx.y) * gridDim.x + blockIdx.x;
    if (tid == 0) {
        float tl = 0.f, tm = 0.f;
        #pragma unroll
        for (int w = 0; w < NTHREADS / 32; w++) { tl += red_l[w]; tm += red_m[w]; }
        g_part[bid] = make_float2(tl, tm);
        __threadfence();
        unsigned int old = atomicAdd(&g_done, 1u);
        s_last = (old == (unsigned)(nblocks - 1)) ? 1 : 0;
    }
    __syncthreads();

    // ---- Last block: final reduction + output + counter reset ----
    if (s_last) {
        double dl = 0.0, dm = 0.0;
        for (int i = tid; i < nblocks; i += NTHREADS) {
            float2 p = __ldcg(&g_part[i]);
            dl += (double)p.x; dm += (double)p.y;
        }
        #pragma unroll
        for (int o = 16; o > 0; o >>= 1) {
            dl += __shfl_down_sync(0xFFFFFFFFu, dl, o);
            dm += __shfl_down_sync(0xFFFFFFFFu, dm, o);
        }
        if (lane == 0) { dred_l[warp] = dl; dred_m[warp] = dm; }
        __syncthreads();
        if (tid == 0) {
            double tl = 0.0, tm = 0.0;
            #pragma unroll
            for (int w = 0; w < NTHREADS / 32; w++) { tl += dred_l[w]; tm += dred_m[w]; }
            out[0] = (float)(tl / tm);
            g_done = 0;   // restore for next graph replay
        }
    }
}

extern "C" void kernel_launch(void* const* d_in, const int* in_sizes, int n_in,
                              void* d_out, int out_size)
{
    const float* pred = (const float*)d_in[0];
    const float* gt   = (const float*)d_in[1];
    const float* mask = (const float*)d_in[2];
    float* out = (float*)d_out;

    const int H = 384;
    const int W = 1280;
    const int B = in_sizes[2] / (H * W);

    dim3 block(32, 8);
    dim3 grid(W / TILE_W, H / TILE_H, B);
    const int nblocks = grid.x * grid.y * grid.z;

    normal_loss_kernel<<<grid, block>>>(pred, gt, mask, out, H, W, nblocks);
}